// round 1
// baseline (speedup 1.0000x reference)
#include <cuda_runtime.h>

#define N_ANG 720
#define N_DET 1024
#define HIMG 512
#define WIMG 512
#define KSZ 11
#define NB 8

// Scratch for the filtered sinogram (allocation-free rule -> __device__ global).
__device__ float g_filt[NB * N_ANG * N_DET];   // 23.6 MB

// ---------------------------------------------------------------------------
// Stage 1: causal cross-correlation along detector axis.
// y[b,a,d] = sum_{k=0..10} w[k] * x[b,a,d+k-10]   (zero outside [0,1024))
// ---------------------------------------------------------------------------
__global__ void conv_kernel(const float* __restrict__ x,
                            const float* __restrict__ w) {
    int idx = blockIdx.x * blockDim.x + threadIdx.x;
    const int total = NB * N_ANG * N_DET;
    if (idx >= total) return;
    int d   = idx & (N_DET - 1);
    int row = idx >> 10;                 // b*N_ANG + a
    const float* xr = x + (long long)row * N_DET;

    float acc = 0.f;
#pragma unroll
    for (int k = 0; k < KSZ; ++k) {
        int s = d + k - (KSZ - 1);       // s <= d <= 1023 always
        float xv = (s >= 0) ? __ldg(xr + s) : 0.f;
        acc = fmaf(__ldg(w + k), xv, acc);
    }
    g_filt[idx] = acc;
}

// ---------------------------------------------------------------------------
// Stage 2: backprojection. One thread = one (i,j) pixel, all 8 batches.
//   t = x*cos(th) + y*sin(th);  u = (t - S0)/DS = x*(c/DS) + y*(s/DS) + 511.5
//   linear interp with boundary masks matching the JAX reference exactly.
// ---------------------------------------------------------------------------
__global__ void __launch_bounds__(256) bp_kernel(float* __restrict__ out) {
    __shared__ float2 trig[N_ANG];       // (cos/DS, sin/DS) per angle

    const float DS  = 4.0f / (float)N_DET;         // 0.00390625
    const float DTH = 3.14159265358979323846f / (float)N_ANG;
    const float DX  = 2.0f / (float)HIMG;

    for (int a = threadIdx.x; a < N_ANG; a += blockDim.x) {
        float th = ((float)a + 0.5f) * DTH;
        float s, c;
        sincosf(th, &s, &c);
        trig[a] = make_float2(c / DS, s / DS);
    }
    __syncthreads();

    int p = blockIdx.x * blockDim.x + threadIdx.x;  // 0 .. H*W-1
    int i = p >> 9;                                  // x index (row of image)
    int j = p & (WIMG - 1);                          // y index (fastest dim)
    float xc = -1.0f + ((float)i + 0.5f) * DX;
    float yc = -1.0f + ((float)j + 0.5f) * DX;

    float acc[NB];
#pragma unroll
    for (int b = 0; b < NB; ++b) acc[b] = 0.f;

#pragma unroll 2
    for (int a = 0; a < N_ANG; ++a) {
        float2 cs = trig[a];
        float u  = fmaf(xc, cs.x, fmaf(yc, cs.y, 511.5f));
        float fi = floorf(u);
        int   i0 = (int)fi;
        float f  = u - fi;

        // masks identical to reference semantics
        float w0 = (i0 >= 0  && i0 <  N_DET    ) ? (1.0f - f) : 0.0f;
        float w1 = (i0 >= -1 && i0 <  N_DET - 1) ? f          : 0.0f;
        int c0 = min(max(i0, 0),     N_DET - 1);
        int c1 = min(max(i0 + 1, 0), N_DET - 1);

        const float* base = g_filt + a * N_DET;
#pragma unroll
        for (int b = 0; b < NB; ++b) {
            float v0 = __ldg(base + b * (N_ANG * N_DET) + c0);
            float v1 = __ldg(base + b * (N_ANG * N_DET) + c1);
            acc[b] = fmaf(w0, v0, fmaf(w1, v1, acc[b]));
        }
    }

#pragma unroll
    for (int b = 0; b < NB; ++b)
        out[b * (HIMG * WIMG) + p] = acc[b] * DTH;
}

// ---------------------------------------------------------------------------
extern "C" void kernel_launch(void* const* d_in, const int* in_sizes, int n_in,
                              void* d_out, int out_size) {
    const float* x = (const float*)d_in[0];   // [8,1,720,1024]
    const float* w = (const float*)d_in[1];   // [1,1,1,11]
    float* out = (float*)d_out;               // [8,1,512,512]

    const int conv_total = NB * N_ANG * N_DET;
    conv_kernel<<<(conv_total + 255) / 256, 256>>>(x, w);
    bp_kernel<<<(HIMG * WIMG) / 256, 256>>>(out);
}

// round 2
// speedup vs baseline: 1.4519x; 1.4519x over previous
#include <cuda_runtime.h>
#include <cuda_fp16.h>

#define N_ANG 720
#define N_DET 1024
#define HIMG 512
#define WIMG 512
#define KSZ 11
#define NB 8

// Filtered sinogram, fp16, layout [angle][det_bin][batch0..7] -> 16B per bin.
// 720*1024*8*2B = 11.8 MB (L2-resident).
__device__ __align__(16) __half g_h[N_ANG * N_DET * NB];

// ---------------------------------------------------------------------------
// Stage 1: causal K=11 cross-correlation along detector axis, all 8 batches
// per thread, output packed as 8 halves (one uint4 store per bin).
// y[b,a,d] = sum_k w[k] * x[b,a,d+k-10]  (zero for index < 0)
// ---------------------------------------------------------------------------
__global__ void conv_kernel(const float* __restrict__ x,
                            const float* __restrict__ w) {
    int idx = blockIdx.x * blockDim.x + threadIdx.x;   // a*1024 + d
    if (idx >= N_ANG * N_DET) return;
    int d = idx & (N_DET - 1);
    int a = idx >> 10;

    float wk[KSZ];
#pragma unroll
    for (int k = 0; k < KSZ; ++k) wk[k] = __ldg(w + k);

    float acc[NB];
#pragma unroll
    for (int b = 0; b < NB; ++b) acc[b] = 0.f;

    const float* xa = x + a * N_DET;
#pragma unroll
    for (int k = 0; k < KSZ; ++k) {
        int s = d + k - (KSZ - 1);
        if (s >= 0) {
#pragma unroll
            for (int b = 0; b < NB; ++b)
                acc[b] = fmaf(wk[k], __ldg(xa + b * (N_ANG * N_DET) + s), acc[b]);
        }
    }

    __half2 h01 = __floats2half2_rn(acc[0], acc[1]);
    __half2 h23 = __floats2half2_rn(acc[2], acc[3]);
    __half2 h45 = __floats2half2_rn(acc[4], acc[5]);
    __half2 h67 = __floats2half2_rn(acc[6], acc[7]);
    uint4 u;
    u.x = *reinterpret_cast<unsigned int*>(&h01);
    u.y = *reinterpret_cast<unsigned int*>(&h23);
    u.z = *reinterpret_cast<unsigned int*>(&h45);
    u.w = *reinterpret_cast<unsigned int*>(&h67);
    reinterpret_cast<uint4*>(g_h)[idx] = u;
}

// ---------------------------------------------------------------------------
// Stage 2: backprojection. One thread = one (i,j) pixel, all 8 batches.
// u in [150.2, 872.8] always -> no boundary masks/clamps needed.
// 2 x LDG.128 per angle fetch both detector bins for all 8 batches.
// Warp footprint 8(j) x 4(i) to keep the detector span compact.
// ---------------------------------------------------------------------------
__global__ void __launch_bounds__(256) bp_kernel(float* __restrict__ out) {
    __shared__ float2 trig[N_ANG];        // (cos/DS, sin/DS)

    const float DTH = 3.14159265358979323846f / (float)N_ANG;
    const float DX  = 2.0f / (float)HIMG;
    const float INV_DS = (float)N_DET / 4.0f;   // 256

    for (int a = threadIdx.x; a < N_ANG; a += blockDim.x) {
        float th = ((float)a + 0.5f) * DTH;
        float s, c;
        sincosf(th, &s, &c);
        trig[a] = make_float2(c * INV_DS, s * INV_DS);
    }
    __syncthreads();

    int tx = threadIdx.x;
    int j = (blockIdx.x << 3) + (tx & 7);   // lane bits 0..2 -> j
    int i = (blockIdx.y << 5) + (tx >> 3);  // lane bits 3..4 (+warp) -> i
    float xc = fmaf((float)i + 0.5f, DX, -1.0f);
    float yc = fmaf((float)j + 0.5f, DX, -1.0f);

    float acc[NB];
#pragma unroll
    for (int b = 0; b < NB; ++b) acc[b] = 0.f;

    const uint4* gp = reinterpret_cast<const uint4*>(g_h);

#pragma unroll 4
    for (int a = 0; a < N_ANG; ++a) {
        float2 cs = trig[a];
        float u = fmaf(xc, cs.x, fmaf(yc, cs.y, 511.5f));
        int   i0 = (int)u;                  // u > 0 -> trunc == floor
        float f  = u - (float)i0;

        const uint4* p = gp + (a << 10) + i0;
        uint4 lo = __ldg(p);                // bin i0,   batches 0..7
        uint4 hi = __ldg(p + 1);            // bin i0+1, batches 0..7

        __half2 f2 = __float2half2_rn(f);
        {
            __half2 l = *reinterpret_cast<__half2*>(&lo.x);
            __half2 h = *reinterpret_cast<__half2*>(&hi.x);
            __half2 s2 = __hfma2(f2, __hsub2(h, l), l);
            float2 sf = __half22float2(s2);
            acc[0] += sf.x; acc[1] += sf.y;
        }
        {
            __half2 l = *reinterpret_cast<__half2*>(&lo.y);
            __half2 h = *reinterpret_cast<__half2*>(&hi.y);
            __half2 s2 = __hfma2(f2, __hsub2(h, l), l);
            float2 sf = __half22float2(s2);
            acc[2] += sf.x; acc[3] += sf.y;
        }
        {
            __half2 l = *reinterpret_cast<__half2*>(&lo.z);
            __half2 h = *reinterpret_cast<__half2*>(&hi.z);
            __half2 s2 = __hfma2(f2, __hsub2(h, l), l);
            float2 sf = __half22float2(s2);
            acc[4] += sf.x; acc[5] += sf.y;
        }
        {
            __half2 l = *reinterpret_cast<__half2*>(&lo.w);
            __half2 h = *reinterpret_cast<__half2*>(&hi.w);
            __half2 s2 = __hfma2(f2, __hsub2(h, l), l);
            float2 sf = __half22float2(s2);
            acc[6] += sf.x; acc[7] += sf.y;
        }
    }

    int p = i * WIMG + j;
#pragma unroll
    for (int b = 0; b < NB; ++b)
        out[b * (HIMG * WIMG) + p] = acc[b] * DTH;
}

// ---------------------------------------------------------------------------
extern "C" void kernel_launch(void* const* d_in, const int* in_sizes, int n_in,
                              void* d_out, int out_size) {
    const float* x = (const float*)d_in[0];   // [8,1,720,1024]
    const float* w = (const float*)d_in[1];   // [1,1,1,11]
    float* out = (float*)d_out;               // [8,1,512,512]

    conv_kernel<<<(N_ANG * N_DET + 255) / 256, 256>>>(x, w);
    dim3 grid(WIMG / 8, HIMG / 32);           // (64, 16)
    bp_kernel<<<grid, 256>>>(out);
}